// round 11
// baseline (speedup 1.0000x reference)
#include <cuda_runtime.h>
#include <math.h>

// ---------------- problem constants ----------------
#define BATCH   32
#define DMODEL  4096
#define NH      32
#define NKV     8
#define GQ      4           // NH / NKV
#define HD      128
#define MAXSEQ  2048
#define BLKSZ   16
#define MAXBLK  128         // MAXSEQ / BLKSZ
#define ATT_SCALE 0.08838834764831845f   // 128^-0.5

#define NQKV    (NH*HD + 2*NKV*HD)       // 6144
#define SPLITS  4
#define NCHUNK  8
#define CHUNK   (MAXSEQ / NCHUNK)        // 256

// ---------------- scratch (device globals; no allocation allowed) --------
__device__ float g_xT[DMODEL * BATCH];                    // xT[k][b]
__device__ float g_qkvT[SPLITS][NQKV * BATCH];            // partial, col-major [col][b]
__device__ float g_q[BATCH * NH * HD];                    // rope'd q, [b][h][d]
__device__ float g_knew[BATCH * NKV * HD];
__device__ float g_vnew[BATCH * NKV * HD];
__device__ float g_pm[BATCH * NH * NCHUNK];
__device__ float g_pl[BATCH * NH * NCHUNK];
__device__ float g_pacc[BATCH * NH * NCHUNK * HD];
__device__ float g_attnT[DMODEL * BATCH];                 // [h*128+d][b]
__device__ float g_oT[SPLITS][DMODEL * BATCH];            // Wo partials, [n][b]

// ---------------- packed f32x2 helpers (sm_103a FFMA2) -------------------
__device__ __forceinline__ void ffma2(unsigned long long& acc,
                                      unsigned long long a,
                                      unsigned long long b) {
    asm("fma.rn.f32x2 %0, %1, %2, %3;" : "=l"(acc) : "l"(a), "l"(b), "l"(acc));
}
__device__ __forceinline__ unsigned long long bcast2(float w) {
    unsigned long long r;
    asm("mov.b64 %0, {%1, %1};" : "=l"(r) : "r"(__float_as_uint(w)));
    return r;
}
__device__ __forceinline__ void add2(unsigned long long& a, unsigned long long b) {
    asm("add.rn.f32x2 %0, %1, %2;" : "=l"(a) : "l"(a), "l"(b));
}

// ---------------- 1) transpose x (32 x 4096) -> xT (4096 x 32) -----------
__global__ void transpose_x_kernel(const float* __restrict__ x) {
    __shared__ float tile[32][33];
    int k0 = blockIdx.x * 32;
    int tx = threadIdx.x;            // 0..31
    int ty = threadIdx.y;            // 0..7
    #pragma unroll
    for (int r = ty; r < 32; r += 8)
        tile[r][tx] = x[r * DMODEL + k0 + tx];     // row b=r, col k0+tx
    __syncthreads();
    #pragma unroll
    for (int r = ty; r < 32; r += 8)
        g_xT[(k0 + r) * BATCH + tx] = tile[tx][r]; // xT[k][b] = x[b][k]
}

// ---------------- 2) GEMM body: Y(32 x N) = x(32 x K) @ W(K x N) ---------
// xT: [K][32]. Each CTA: 64 columns, one K-split, 256 threads.
// thread = (kr 0..7, nc 0..31); owns cols n0=base+nc and n0+32,
// accumulates all 32 batches as 16 packed f32x2 pairs per column.
#define GT  256
#define GBK 128

__device__ __forceinline__ void gemm_body(
    const float* __restrict__ xT, const float* __restrict__ W, int N,
    float* __restrict__ outT, int wcolbase, int outcolbase,
    int k0, int ksz)
{
    __shared__ __align__(16) float xs[GBK * 32];              // 16 KB
    __shared__ unsigned long long red[4 * 32 * 16];           // 16 KB

    const int tid = threadIdx.x;
    const int nc = tid & 31;
    const int kr = tid >> 5;
    const int n0 = wcolbase + nc;
    const int n1 = n0 + 32;

    unsigned long long acc0[16], acc1[16];
    #pragma unroll
    for (int p = 0; p < 16; p++) { acc0[p] = 0ull; acc1[p] = 0ull; }

    for (int kk = 0; kk < ksz; kk += GBK) {
        const int kbase = k0 + kk;
        __syncthreads();
        // cooperative load of xT chunk (GBK x 32 floats, contiguous)
        {
            const float4* src = (const float4*)(xT + (size_t)kbase * 32);
            float4* dst = (float4*)xs;
            #pragma unroll
            for (int i = tid; i < GBK * 8; i += GT) dst[i] = src[i];
        }
        __syncthreads();

        #pragma unroll 2
        for (int i = 0; i < GBK / 8; i++) {
            const int kl = kr + 8 * i;
            const float w0 = __ldg(&W[(size_t)(kbase + kl) * N + n0]);
            const float w1 = __ldg(&W[(size_t)(kbase + kl) * N + n1]);
            const unsigned long long w0p = bcast2(w0);
            const unsigned long long w1p = bcast2(w1);
            const unsigned long long* xr =
                (const unsigned long long*)(xs + kl * 32);
            #pragma unroll
            for (int p = 0; p < 16; p++) {
                const unsigned long long xp = xr[p];
                ffma2(acc0[p], xp, w0p);
                ffma2(acc1[p], xp, w1p);
            }
        }
    }

    // reduce over kr (8 partial sums per column) via smem tree
    for (int half = 0; half < 2; half++) {
        unsigned long long* A = half ? acc1 : acc0;
        #pragma unroll
        for (int off = 4; off >= 1; off >>= 1) {
            __syncthreads();
            if (kr >= off && kr < 2 * off) {
                unsigned long long* d = red + ((kr - off) * 32 + nc) * 16;
                #pragma unroll
                for (int p = 0; p < 16; p++) d[p] = A[p];
            }
            __syncthreads();
            if (kr < off) {
                const unsigned long long* s = red + (kr * 32 + nc) * 16;
                #pragma unroll
                for (int p = 0; p < 16; p++) add2(A[p], s[p]);
            }
        }
    }

    if (kr == 0) {
        unsigned long long* o0 =
            (unsigned long long*)(outT + (size_t)(outcolbase + nc) * BATCH);
        unsigned long long* o1 =
            (unsigned long long*)(outT + (size_t)(outcolbase + nc + 32) * BATCH);
        #pragma unroll
        for (int p = 0; p < 16; p++) { o0[p] = acc0[p]; o1[p] = acc1[p]; }
    }
}

__global__ __launch_bounds__(GT, 2) void qkv_gemm_kernel(
    const float* __restrict__ Wq, const float* __restrict__ Wk,
    const float* __restrict__ Wv)
{
    const int tile  = blockIdx.x;          // 0..95
    const int split = blockIdx.y;          // 0..3
    const int ksz = DMODEL / SPLITS;       // 1024
    const int k0  = split * ksz;
    const float* W; int N, wcb, ocb;
    if (tile < 64)      { W = Wq; N = 4096; wcb = tile * 64;        ocb = tile * 64; }
    else if (tile < 80) { W = Wk; N = 1024; wcb = (tile - 64) * 64; ocb = 4096 + (tile - 64) * 64; }
    else                { W = Wv; N = 1024; wcb = (tile - 80) * 64; ocb = 5120 + (tile - 80) * 64; }
    gemm_body(g_xT, W, N, g_qkvT[split], wcb, ocb, k0, ksz);
}

__global__ __launch_bounds__(GT, 2) void wo_gemm_kernel(const float* __restrict__ Wo) {
    const int tile  = blockIdx.x;          // 0..63
    const int split = blockIdx.y;          // 0..3
    gemm_body(g_attnT, Wo, 4096, g_oT[split],
              tile * 64, tile * 64, split * 1024, 1024);
}

// ---------------- 3) split-sum + RoPE -------------------------------------
// grid (48 rows, 32 b), 64 threads (j = rotation pair index)
__global__ void rope_kernel(const int* __restrict__ ctx) {
    const int row = blockIdx.x;    // 0..31 q heads, 32..39 k heads, 40..47 v heads
    const int b   = blockIdx.y;
    const int j   = threadIdx.x;   // 0..63
    const int pos = ctx[b] - 1;

    int colbase;
    float* out;
    if (row < 32)      { colbase = row * HD;                 out = g_q    + (b * NH  + row)        * HD; }
    else if (row < 40) { colbase = 4096 + (row - 32) * HD;   out = g_knew + (b * NKV + (row - 32)) * HD; }
    else               { colbase = 5120 + (row - 40) * HD;   out = g_vnew + (b * NKV + (row - 40)) * HD; }

    float v0 = 0.f, v1 = 0.f;
    #pragma unroll
    for (int s = 0; s < SPLITS; s++) {
        v0 += g_qkvT[s][(colbase + j)      * BATCH + b];
        v1 += g_qkvT[s][(colbase + j + 64) * BATCH + b];
    }

    if (row < 40) {
        // inv_freq = 10000^(-j/64) = exp2(-j * log2(10000)/64)
        const float inv = exp2f(-(float)j * 0.20762050593046014f);
        const float ang = (float)pos * inv;
        float sn, cs;
        sincosf(ang, &sn, &cs);
        out[j]      = v0 * cs - v1 * sn;
        out[j + 64] = v0 * sn + v1 * cs;
    } else {
        out[j]      = v0;
        out[j + 64] = v1;
    }
}

// ---------------- 4) split-KV paged attention -----------------------------
// grid (chunk=8, kv=8, b=32), 128 threads = 4 warps; warp strides t by 4.
__global__ __launch_bounds__(128) void attn_kernel(
    const float* __restrict__ kcache, const float* __restrict__ vcache,
    const int* __restrict__ btab, const int* __restrict__ ctx)
{
    const int c  = blockIdx.x;
    const int kv = blockIdx.y;
    const int b  = blockIdx.z;
    const int tid  = threadIdx.x;
    const int wid  = tid >> 5;
    const int lane = tid & 31;

    const int len  = ctx[b];
    const int pos  = len - 1;
    const int t0   = c * CHUNK;
    const int tend = min(t0 + CHUNK, len);

    // q slices (4 heads sharing this kv head); lane owns d = 4*lane..4*lane+3
    float4 qv[GQ];
    #pragma unroll
    for (int g = 0; g < GQ; g++)
        qv[g] = ((const float4*)(g_q + (size_t)(b * NH + kv * GQ + g) * HD))[lane];

    float  m[GQ], l[GQ];
    float4 acc[GQ];
    #pragma unroll
    for (int g = 0; g < GQ; g++) {
        m[g] = -1e30f; l[g] = 0.f;
        acc[g] = make_float4(0.f, 0.f, 0.f, 0.f);
    }

    const int* bt = btab + b * MAXBLK;
    const float4* knew4 = (const float4*)(g_knew + (size_t)(b * NKV + kv) * HD);
    const float4* vnew4 = (const float4*)(g_vnew + (size_t)(b * NKV + kv) * HD);

    for (int t = t0 + wid; t < tend; t += 4) {
        const float4 *kr, *vr;
        if (t == pos) { kr = knew4; vr = vnew4; }
        else {
            const int slot = bt[t >> 4] * BLKSZ + (t & 15);
            const size_t base = (size_t)slot * (NKV * HD) + (size_t)kv * HD;
            kr = (const float4*)(kcache + base);
            vr = (const float4*)(vcache + base);
        }
        const float4 k4 = kr[lane];
        const float4 v4 = vr[lane];

        float s0 = qv[0].x*k4.x + qv[0].y*k4.y + qv[0].z*k4.z + qv[0].w*k4.w;
        float s1 = qv[1].x*k4.x + qv[1].y*k4.y + qv[1].z*k4.z + qv[1].w*k4.w;
        float s2 = qv[2].x*k4.x + qv[2].y*k4.y + qv[2].z*k4.z + qv[2].w*k4.w;
        float s3 = qv[3].x*k4.x + qv[3].y*k4.y + qv[3].z*k4.z + qv[3].w*k4.w;
        #pragma unroll
        for (int o = 16; o; o >>= 1) {
            s0 += __shfl_xor_sync(0xffffffffu, s0, o);
            s1 += __shfl_xor_sync(0xffffffffu, s1, o);
            s2 += __shfl_xor_sync(0xffffffffu, s2, o);
            s3 += __shfl_xor_sync(0xffffffffu, s3, o);
        }
        float sc[GQ] = { s0 * ATT_SCALE, s1 * ATT_SCALE,
                         s2 * ATT_SCALE, s3 * ATT_SCALE };
        #pragma unroll
        for (int g = 0; g < GQ; g++) {
            const float sg = sc[g];
            if (sg > m[g]) {                       // warp-uniform branch; rare after warmup
                const float f = __expf(m[g] - sg);
                m[g] = sg;
                l[g] = fmaf(l[g], f, 1.0f);
                acc[g].x = fmaf(acc[g].x, f, v4.x);
                acc[g].y = fmaf(acc[g].y, f, v4.y);
                acc[g].z = fmaf(acc[g].z, f, v4.z);
                acc[g].w = fmaf(acc[g].w, f, v4.w);
            } else {
                const float p = __expf(sg - m[g]);
                l[g] += p;
                acc[g].x = fmaf(p, v4.x, acc[g].x);
                acc[g].y = fmaf(p, v4.y, acc[g].y);
                acc[g].z = fmaf(p, v4.z, acc[g].z);
                acc[g].w = fmaf(p, v4.w, acc[g].w);
            }
        }
    }

    // merge the 4 warps' online-softmax states in SMEM
    __shared__ float sm[4][GQ], sl[4][GQ];
    __shared__ __align__(16) float sacc[4][GQ][HD];
    #pragma unroll
    for (int g = 0; g < GQ; g++) {
        ((float4*)sacc[wid][g])[lane] = acc[g];
        if (lane == 0) { sm[wid][g] = m[g]; sl[wid][g] = l[g]; }
    }
    __syncthreads();

    const int d = tid;   // 128 threads == HD
    #pragma unroll
    for (int g = 0; g < GQ; g++) {
        float ms = -1e30f;
        #pragma unroll
        for (int w = 0; w < 4; w++) ms = fmaxf(ms, sm[w][g]);
        float L = 0.f, A = 0.f;
        #pragma unroll
        for (int w = 0; w < 4; w++) {
            const float f = __expf(sm[w][g] - ms);
            L += sl[w][g] * f;
            A += sacc[w][g][d] * f;
        }
        const int pidx = ((b * NH + kv * GQ + g) * NCHUNK + c);
        g_pacc[(size_t)pidx * HD + d] = A;
        if (d == 0) { g_pm[pidx] = ms; g_pl[pidx] = L; }
    }
}

// combine 8 chunk partials per (b,h); write attnT for the Wo GEMM
__global__ __launch_bounds__(HD) void attn_combine_kernel() {
    const int bh = blockIdx.x;        // 0..1023
    const int d  = threadIdx.x;       // 0..127
    float ms = -1e30f;
    #pragma unroll
    for (int c = 0; c < NCHUNK; c++) ms = fmaxf(ms, g_pm[bh * NCHUNK + c]);
    float L = 0.f, A = 0.f;
    #pragma unroll
    for (int c = 0; c < NCHUNK; c++) {
        const float f = __expf(g_pm[bh * NCHUNK + c] - ms);
        L += g_pl[bh * NCHUNK + c] * f;
        A += g_pacc[(size_t)(bh * NCHUNK + c) * HD + d] * f;
    }
    const float o = A / L;
    const int b = bh >> 5;
    const int h = bh & 31;
    g_attnT[(size_t)(h * HD + d) * BATCH + b] = o;
}

// ---------------- 5) sum Wo split partials -> d_out -----------------------
__global__ void out_combine_kernel(float* __restrict__ out) {
    const int i = blockIdx.x * 256 + threadIdx.x;   // 131072 total
    const int n = i >> 5;
    const int b = i & 31;
    float v = 0.f;
    #pragma unroll
    for (int s = 0; s < SPLITS; s++) v += g_oT[s][(size_t)n * BATCH + b];
    out[(size_t)b * DMODEL + n] = v;
}

// ---------------- launcher -------------------------------------------------
extern "C" void kernel_launch(void* const* d_in, const int* in_sizes, int n_in,
                              void* d_out, int out_size) {
    const float* x   = (const float*)d_in[0];
    const float* Wq  = (const float*)d_in[1];
    const float* Wk  = (const float*)d_in[2];
    const float* Wv  = (const float*)d_in[3];
    const float* Wo  = (const float*)d_in[4];
    const float* kc  = (const float*)d_in[5];
    const float* vc  = (const float*)d_in[6];
    const int*   bt  = (const int*)d_in[7];
    const int*   ctx = (const int*)d_in[8];
    float* out = (float*)d_out;

    transpose_x_kernel<<<DMODEL / 32, dim3(32, 8)>>>(x);
    qkv_gemm_kernel<<<dim3(96, SPLITS), GT>>>(Wq, Wk, Wv);
    rope_kernel<<<dim3(48, BATCH), 64>>>(ctx);
    attn_kernel<<<dim3(NCHUNK, NKV, BATCH), 128>>>(kc, vc, bt, ctx);
    attn_combine_kernel<<<BATCH * NH, HD>>>();
    wo_gemm_kernel<<<dim3(64, SPLITS), GT>>>(Wo);
    out_combine_kernel<<<(BATCH * DMODEL) / 256, 256>>>(out);
}

// round 12
// speedup vs baseline: 1.1671x; 1.1671x over previous
#include <cuda_runtime.h>
#include <math.h>

// ---------------- problem constants ----------------
#define BATCH   32
#define DMODEL  4096
#define NH      32
#define NKV     8
#define GQ      4           // NH / NKV
#define HD      128
#define MAXSEQ  2048
#define BLKSZ   16
#define MAXBLK  128         // MAXSEQ / BLKSZ
#define ATT_SCALE 0.08838834764831845f   // 128^-0.5

#define NQKV    (NH*HD + 2*NKV*HD)       // 6144
#define SPLITS  4
#define NCHUNK  8

// ---------------- scratch (device globals; no allocation allowed) --------
__device__ float g_xT[DMODEL * BATCH];                    // xT[k][b]
__device__ float g_qkvT[SPLITS][NQKV * BATCH];            // partial, col-major [col][b]
__device__ float g_q[BATCH * NH * HD];                    // rope'd q, [b][h][d]
__device__ float g_knew[BATCH * NKV * HD];
__device__ float g_vnew[BATCH * NKV * HD];
__device__ float g_pm[BATCH * NH * NCHUNK];
__device__ float g_pl[BATCH * NH * NCHUNK];
__device__ float g_pacc[BATCH * NH * NCHUNK * HD];
__device__ float g_attnT[DMODEL * BATCH];                 // [h*128+d][b]
__device__ float g_oT[SPLITS][DMODEL * BATCH];            // Wo partials, [n][b]

// ---------------- packed f32x2 helpers (sm_103a FFMA2) -------------------
__device__ __forceinline__ void ffma2(unsigned long long& acc,
                                      unsigned long long a,
                                      unsigned long long b) {
    asm("fma.rn.f32x2 %0, %1, %2, %3;" : "=l"(acc) : "l"(a), "l"(b), "l"(acc));
}
__device__ __forceinline__ unsigned long long bcast2(float w) {
    unsigned long long r;
    asm("mov.b64 %0, {%1, %1};" : "=l"(r) : "r"(__float_as_uint(w)));
    return r;
}
__device__ __forceinline__ void add2(unsigned long long& a, unsigned long long b) {
    asm("add.rn.f32x2 %0, %1, %2;" : "=l"(a) : "l"(a), "l"(b));
}

// ---------------- 1) transpose x (32 x 4096) -> xT (4096 x 32) -----------
__global__ void transpose_x_kernel(const float* __restrict__ x) {
    __shared__ float tile[32][33];
    int k0 = blockIdx.x * 32;
    int tx = threadIdx.x;            // 0..31
    int ty = threadIdx.y;            // 0..7
    #pragma unroll
    for (int r = ty; r < 32; r += 8)
        tile[r][tx] = x[r * DMODEL + k0 + tx];
    __syncthreads();
    #pragma unroll
    for (int r = ty; r < 32; r += 8)
        g_xT[(k0 + r) * BATCH + tx] = tile[tx][r];
}

// ---------------- 2) GEMM body: Y(32 x N) = x(32 x K) @ W(K x N) ---------
// xT: [K][32]. Each CTA: 64 columns, one K-split, 256 threads.
// thread = (kr 0..7, nc 0..31); owns cols n0 and n0+32, accumulates all 32
// batches as 16 packed f32x2 pairs per column. Weights for 8 k-rows are
// prefetched into registers before each FFMA2 burst so ~16 LDGs sit in
// flight per warp (covers DRAM latency).
#define GT  256
#define GBK 128

__device__ __forceinline__ void gemm_body(
    const float* __restrict__ xT, const float* __restrict__ W, int N,
    float* __restrict__ outT, int wcolbase, int outcolbase,
    int k0, int ksz)
{
    __shared__ __align__(16) float xs[GBK * 32];              // 16 KB
    __shared__ unsigned long long red[4 * 32 * 16];           // 16 KB

    const int tid = threadIdx.x;
    const int nc = tid & 31;
    const int kr = tid >> 5;
    const int n0 = wcolbase + nc;
    const int n1 = n0 + 32;

    unsigned long long acc0[16], acc1[16];
    #pragma unroll
    for (int p = 0; p < 16; p++) { acc0[p] = 0ull; acc1[p] = 0ull; }

    for (int kk = 0; kk < ksz; kk += GBK) {
        const int kbase = k0 + kk;
        __syncthreads();
        {
            const float4* src = (const float4*)(xT + (size_t)kbase * 32);
            float4* dst = (float4*)xs;
            #pragma unroll
            for (int i = tid; i < GBK * 8; i += GT) dst[i] = src[i];
        }
        __syncthreads();

        #pragma unroll
        for (int half = 0; half < 2; half++) {
            // ---- batched weight prefetch: 16 independent LDGs ----
            float wa[8], wb[8];
            #pragma unroll
            for (int i = 0; i < 8; i++) {
                const size_t row = (size_t)(kbase + half * 64 + kr + 8 * i) * N;
                wa[i] = __ldg(&W[row + n0]);
                wb[i] = __ldg(&W[row + n1]);
            }
            // ---- FFMA2 burst ----
            #pragma unroll
            for (int i = 0; i < 8; i++) {
                const unsigned long long w0p = bcast2(wa[i]);
                const unsigned long long w1p = bcast2(wb[i]);
                const unsigned long long* xr =
                    (const unsigned long long*)(xs + (half * 64 + kr + 8 * i) * 32);
                #pragma unroll
                for (int p = 0; p < 16; p++) {
                    const unsigned long long xp = xr[p];
                    ffma2(acc0[p], xp, w0p);
                    ffma2(acc1[p], xp, w1p);
                }
            }
        }
    }

    // reduce over kr (8 partial sums per column) via smem tree
    for (int half = 0; half < 2; half++) {
        unsigned long long* A = half ? acc1 : acc0;
        #pragma unroll
        for (int off = 4; off >= 1; off >>= 1) {
            __syncthreads();
            if (kr >= off && kr < 2 * off) {
                unsigned long long* d = red + ((kr - off) * 32 + nc) * 16;
                #pragma unroll
                for (int p = 0; p < 16; p++) d[p] = A[p];
            }
            __syncthreads();
            if (kr < off) {
                const unsigned long long* s = red + (kr * 32 + nc) * 16;
                #pragma unroll
                for (int p = 0; p < 16; p++) add2(A[p], s[p]);
            }
        }
    }

    if (kr == 0) {
        unsigned long long* o0 =
            (unsigned long long*)(outT + (size_t)(outcolbase + nc) * BATCH);
        unsigned long long* o1 =
            (unsigned long long*)(outT + (size_t)(outcolbase + nc + 32) * BATCH);
        #pragma unroll
        for (int p = 0; p < 16; p++) { o0[p] = acc0[p]; o1[p] = acc1[p]; }
    }
}

__global__ __launch_bounds__(GT, 2) void qkv_gemm_kernel(
    const float* __restrict__ Wq, const float* __restrict__ Wk,
    const float* __restrict__ Wv)
{
    const int tile  = blockIdx.x;          // 0..95
    const int split = blockIdx.y;          // 0..3
    const int ksz = DMODEL / SPLITS;       // 1024
    const int k0  = split * ksz;
    const float* W; int N, wcb, ocb;
    if (tile < 64)      { W = Wq; N = 4096; wcb = tile * 64;        ocb = tile * 64; }
    else if (tile < 80) { W = Wk; N = 1024; wcb = (tile - 64) * 64; ocb = 4096 + (tile - 64) * 64; }
    else                { W = Wv; N = 1024; wcb = (tile - 80) * 64; ocb = 5120 + (tile - 80) * 64; }
    gemm_body(g_xT, W, N, g_qkvT[split], wcb, ocb, k0, ksz);
}

__global__ __launch_bounds__(GT, 2) void wo_gemm_kernel(const float* __restrict__ Wo) {
    const int tile  = blockIdx.x;          // 0..63
    const int split = blockIdx.y;          // 0..3
    gemm_body(g_attnT, Wo, 4096, g_oT[split],
              tile * 64, tile * 64, split * 1024, 1024);
}

// ---------------- 3) split-sum + RoPE -------------------------------------
__global__ void rope_kernel(const int* __restrict__ ctx) {
    const int row = blockIdx.x;    // 0..31 q heads, 32..39 k heads, 40..47 v heads
    const int b   = blockIdx.y;
    const int j   = threadIdx.x;   // 0..63
    const int pos = ctx[b] - 1;

    int colbase;
    float* out;
    if (row < 32)      { colbase = row * HD;                 out = g_q    + (b * NH  + row)        * HD; }
    else if (row < 40) { colbase = 4096 + (row - 32) * HD;   out = g_knew + (b * NKV + (row - 32)) * HD; }
    else               { colbase = 5120 + (row - 40) * HD;   out = g_vnew + (b * NKV + (row - 40)) * HD; }

    float v0 = 0.f, v1 = 0.f;
    #pragma unroll
    for (int s = 0; s < SPLITS; s++) {
        v0 += g_qkvT[s][(colbase + j)      * BATCH + b];
        v1 += g_qkvT[s][(colbase + j + 64) * BATCH + b];
    }

    if (row < 40) {
        const float inv = exp2f(-(float)j * 0.20762050593046014f);
        const float ang = (float)pos * inv;
        float sn, cs;
        sincosf(ang, &sn, &cs);
        out[j]      = v0 * cs - v1 * sn;
        out[j + 64] = v0 * sn + v1 * cs;
    } else {
        out[j]      = v0;
        out[j + 64] = v1;
    }
}

// ---------------- 4) split-KV paged attention -----------------------------
// grid (chunk=8, kv=8, b=32), 128 threads = 4 warps.
// Length-proportional chunking: chunk c covers [c*len/8, (c+1)*len/8) — all
// CTAs carry equal work. Block-table slice staged in SMEM. K/V rows flow
// through a depth-2 register pipeline (4 LDG.128 in flight per warp).
__global__ __launch_bounds__(128) void attn_kernel(
    const float* __restrict__ kcache, const float* __restrict__ vcache,
    const int* __restrict__ btab, const int* __restrict__ ctx)
{
    const int c  = blockIdx.x;
    const int kv = blockIdx.y;
    const int b  = blockIdx.z;
    const int tid  = threadIdx.x;
    const int wid  = tid >> 5;
    const int lane = tid & 31;

    const int len  = ctx[b];
    const int pos  = len - 1;
    const int t0   = (c * len) >> 3;        // NCHUNK = 8
    const int tend = ((c + 1) * len) >> 3;

    // stage block table slice (<=17 entries per chunk)
    __shared__ int sbt[20];
    const int blk0 = t0 >> 4;
    if (tend > t0) {
        const int nblk = ((tend - 1) >> 4) - blk0 + 1;
        if (tid < nblk) sbt[tid] = btab[b * MAXBLK + blk0 + tid];
    }
    __syncthreads();

    float4 qv[GQ];
    #pragma unroll
    for (int g = 0; g < GQ; g++)
        qv[g] = ((const float4*)(g_q + (size_t)(b * NH + kv * GQ + g) * HD))[lane];

    float  m[GQ], l[GQ];
    float4 acc[GQ];
    #pragma unroll
    for (int g = 0; g < GQ; g++) {
        m[g] = -1e30f; l[g] = 0.f;
        acc[g] = make_float4(0.f, 0.f, 0.f, 0.f);
    }

    const float4* knew4 = (const float4*)(g_knew + (size_t)(b * NKV + kv) * HD);
    const float4* vnew4 = (const float4*)(g_vnew + (size_t)(b * NKV + kv) * HD);

    #define LOADKV(tt, kk, vv) do {                                         \
        const float4 *krp_, *vrp_;                                          \
        if ((tt) == pos) { krp_ = knew4; vrp_ = vnew4; }                     \
        else {                                                               \
            const int slot_ = sbt[((tt) >> 4) - blk0] * BLKSZ + ((tt) & 15); \
            const size_t base_ = (size_t)slot_ * (NKV * HD) + (size_t)kv * HD; \
            krp_ = (const float4*)(kcache + base_);                          \
            vrp_ = (const float4*)(vcache + base_);                          \
        }                                                                    \
        kk = krp_[lane]; vv = vrp_[lane];                                    \
    } while (0)

    // depth-2 software pipeline over tokens (warp stride 4)
    int t = t0 + wid;
    float4 k0r, v0r, k1r, v1r;
    if (t < tend)     LOADKV(t, k0r, v0r);
    if (t + 4 < tend) LOADKV(t + 4, k1r, v1r);

    for (; t < tend; t += 4) {
        float4 kn, vn;
        if (t + 8 < tend) LOADKV(t + 8, kn, vn);

        const float4 k4 = k0r, v4 = v0r;

        float s0 = qv[0].x*k4.x + qv[0].y*k4.y + qv[0].z*k4.z + qv[0].w*k4.w;
        float s1 = qv[1].x*k4.x + qv[1].y*k4.y + qv[1].z*k4.z + qv[1].w*k4.w;
        float s2 = qv[2].x*k4.x + qv[2].y*k4.y + qv[2].z*k4.z + qv[2].w*k4.w;
        float s3 = qv[3].x*k4.x + qv[3].y*k4.y + qv[3].z*k4.z + qv[3].w*k4.w;
        #pragma unroll
        for (int o = 16; o; o >>= 1) {
            s0 += __shfl_xor_sync(0xffffffffu, s0, o);
            s1 += __shfl_xor_sync(0xffffffffu, s1, o);
            s2 += __shfl_xor_sync(0xffffffffu, s2, o);
            s3 += __shfl_xor_sync(0xffffffffu, s3, o);
        }
        float sc[GQ] = { s0 * ATT_SCALE, s1 * ATT_SCALE,
                         s2 * ATT_SCALE, s3 * ATT_SCALE };
        #pragma unroll
        for (int g = 0; g < GQ; g++) {
            const float sg = sc[g];
            if (sg > m[g]) {                       // warp-uniform; rare after warmup
                const float f = __expf(m[g] - sg);
                m[g] = sg;
                l[g] = fmaf(l[g], f, 1.0f);
                acc[g].x = fmaf(acc[g].x, f, v4.x);
                acc[g].y = fmaf(acc[g].y, f, v4.y);
                acc[g].z = fmaf(acc[g].z, f, v4.z);
                acc[g].w = fmaf(acc[g].w, f, v4.w);
            } else {
                const float p = __expf(sg - m[g]);
                l[g] += p;
                acc[g].x = fmaf(p, v4.x, acc[g].x);
                acc[g].y = fmaf(p, v4.y, acc[g].y);
                acc[g].z = fmaf(p, v4.z, acc[g].z);
                acc[g].w = fmaf(p, v4.w, acc[g].w);
            }
        }

        k0r = k1r; v0r = v1r;
        k1r = kn;  v1r = vn;
    }
    #undef LOADKV

    // merge the 4 warps' online-softmax states in SMEM
    __shared__ float smx[4][GQ], sl[4][GQ];
    __shared__ __align__(16) float sacc[4][GQ][HD];
    #pragma unroll
    for (int g = 0; g < GQ; g++) {
        ((float4*)sacc[wid][g])[lane] = acc[g];
        if (lane == 0) { smx[wid][g] = m[g]; sl[wid][g] = l[g]; }
    }
    __syncthreads();

    const int d = tid;   // 128 threads == HD
    #pragma unroll
    for (int g = 0; g < GQ; g++) {
        float ms = -1e30f;
        #pragma unroll
        for (int w = 0; w < 4; w++) ms = fmaxf(ms, smx[w][g]);
        float L = 0.f, A = 0.f;
        #pragma unroll
        for (int w = 0; w < 4; w++) {
            const float f = __expf(smx[w][g] - ms);
            L += sl[w][g] * f;
            A += sacc[w][g][d] * f;
        }
        const int pidx = ((b * NH + kv * GQ + g) * NCHUNK + c);
        g_pacc[(size_t)pidx * HD + d] = A;
        if (d == 0) { g_pm[pidx] = ms; g_pl[pidx] = L; }
    }
}

// combine 8 chunk partials per (b,h); write attnT for the Wo GEMM
__global__ __launch_bounds__(HD) void attn_combine_kernel() {
    const int bh = blockIdx.x;        // 0..1023
    const int d  = threadIdx.x;       // 0..127
    float ms = -1e30f;
    #pragma unroll
    for (int c = 0; c < NCHUNK; c++) ms = fmaxf(ms, g_pm[bh * NCHUNK + c]);
    float L = 0.f, A = 0.f;
    #pragma unroll
    for (int c = 0; c < NCHUNK; c++) {
        const float f = __expf(g_pm[bh * NCHUNK + c] - ms);
        L += g_pl[bh * NCHUNK + c] * f;
        A += g_pacc[(size_t)(bh * NCHUNK + c) * HD + d] * f;
    }
    const float o = A / L;
    const int b = bh >> 5;
    const int h = bh & 31;
    g_attnT[(size_t)(h * HD + d) * BATCH + b] = o;
}

// ---------------- 5) sum Wo split partials -> d_out -----------------------
__global__ void out_combine_kernel(float* __restrict__ out) {
    const int i = blockIdx.x * 256 + threadIdx.x;   // 131072 total
    const int n = i >> 5;
    const int b = i & 31;
    float v = 0.f;
    #pragma unroll
    for (int s = 0; s < SPLITS; s++) v += g_oT[s][(size_t)n * BATCH + b];
    out[(size_t)b * DMODEL + n] = v;
}

// ---------------- launcher -------------------------------------------------
extern "C" void kernel_launch(void* const* d_in, const int* in_sizes, int n_in,
                              void* d_out, int out_size) {
    const float* x   = (const float*)d_in[0];
    const float* Wq  = (const float*)d_in[1];
    const float* Wk  = (const float*)d_in[2];
    const float* Wv  = (const float*)d_in[3];
    const float* Wo  = (const float*)d_in[4];
    const float* kc  = (const float*)d_in[5];
    const float* vc  = (const float*)d_in[6];
    const int*   bt  = (const int*)d_in[7];
    const int*   ctx = (const int*)d_in[8];
    float* out = (float*)d_out;

    transpose_x_kernel<<<DMODEL / 32, dim3(32, 8)>>>(x);
    qkv_gemm_kernel<<<dim3(96, SPLITS), GT>>>(Wq, Wk, Wv);
    rope_kernel<<<dim3(48, BATCH), 64>>>(ctx);
    attn_kernel<<<dim3(NCHUNK, NKV, BATCH), 128>>>(kc, vc, bt, ctx);
    attn_combine_kernel<<<BATCH * NH, HD>>>();
    wo_gemm_kernel<<<dim3(64, SPLITS), GT>>>(Wo);
    out_combine_kernel<<<(BATCH * DMODEL) / 256, 256>>>(out);
}